// round 16
// baseline (speedup 1.0000x reference)
#include <cuda_runtime.h>
#include <cuda_bf16.h>
#include <cstdint>

#define N_NODES 50000
#define N_EDGES_MAX 600000
#define D 128
#define N_CLASSES 40

#define SCAN_BLK 1024
#define SCAN_NBLK ((N_NODES + SCAN_BLK - 1) / SCAN_BLK)   // 49

// Scratch (static device globals — no allocations allowed).
// Only dereferenced from DEVICE code; host only takes addresses via API.
__device__ float g_acc[N_NODES * D];   // z = h W^T (GEMM output / gather input)
__device__ float g_buf0[N_NODES * D];  // h1
__device__ float g_buf1[N_NODES * D];  // h2
__device__ int   g_cnt[N_NODES];
__device__ int   g_row[N_NODES + 1];
__device__ int   g_cur[N_NODES];
__device__ int   g_esrc[N_EDGES_MAX];
__device__ int   g_bsum[SCAN_NBLK];

// ---------------------------------------------------------------------------
// CSR build (4 edges per thread)
// ---------------------------------------------------------------------------
__global__ void gcn_hist_kernel(const int* __restrict__ dst, int n_edges) {
    int e0 = (blockIdx.x * blockDim.x + threadIdx.x) * 4;
    if (e0 + 3 < n_edges) {
        int4 d = *(const int4*)(dst + e0);
        atomicAdd(&g_cnt[d.x], 1);
        atomicAdd(&g_cnt[d.y], 1);
        atomicAdd(&g_cnt[d.z], 1);
        atomicAdd(&g_cnt[d.w], 1);
    } else {
        for (int e = e0; e < n_edges; e++) atomicAdd(&g_cnt[dst[e]], 1);
    }
}

__global__ void gcn_scanA_kernel() {
    __shared__ int sh[SCAN_BLK];
    int t = threadIdx.x;
    int idx = blockIdx.x * SCAN_BLK + t;
    int v = (idx < N_NODES) ? g_cnt[idx] : 0;
    sh[t] = v;
    __syncthreads();
    for (int off = 1; off < SCAN_BLK; off <<= 1) {
        int u = (t >= off) ? sh[t - off] : 0;
        __syncthreads();
        sh[t] += u;
        __syncthreads();
    }
    if (idx < N_NODES) g_row[idx] = sh[t] - v;
    if (t == SCAN_BLK - 1) g_bsum[blockIdx.x] = sh[t];
}

__global__ void gcn_scanB_kernel() {
    __shared__ int sh[64];
    __shared__ int s_off;
    int t = threadIdx.x;
    int blk = blockIdx.x;
    if (t < 64) sh[t] = (t < SCAN_NBLK) ? g_bsum[t] : 0;
    __syncthreads();
    if (t == 0) {
        int o = 0;
#pragma unroll 7
        for (int b = 0; b < blk; b++) o += sh[b];
        s_off = o;
    }
    __syncthreads();
    int off = s_off;
    int idx = blk * SCAN_BLK + t;
    if (idx < N_NODES) {
        int r = g_row[idx] + off;
        g_row[idx] = r;
        g_cur[idx] = r;
        if (idx == N_NODES - 1) g_row[N_NODES] = r + g_cnt[idx];
    }
}

__global__ void gcn_fill_kernel(const int* __restrict__ src,
                                const int* __restrict__ dst, int n_edges) {
    int e0 = (blockIdx.x * blockDim.x + threadIdx.x) * 4;
    if (e0 + 3 < n_edges) {
        int4 s = *(const int4*)(src + e0);
        int4 d = *(const int4*)(dst + e0);
        int p0 = atomicAdd(&g_cur[d.x], 1);
        int p1 = atomicAdd(&g_cur[d.y], 1);
        int p2 = atomicAdd(&g_cur[d.z], 1);
        int p3 = atomicAdd(&g_cur[d.w], 1);
        g_esrc[p0] = s.x; g_esrc[p1] = s.y; g_esrc[p2] = s.z; g_esrc[p3] = s.w;
    } else {
        for (int e = e0; e < n_edges; e++) {
            int pos = atomicAdd(&g_cur[dst[e]], 1);
            g_esrc[pos] = src[e];
        }
    }
}

// ---------------------------------------------------------------------------
// Buffer selection by template (device-symbol addresses stay device-side).
// SEL: 0 = param pointer, 1 = g_buf0, 2 = g_buf1
// ---------------------------------------------------------------------------
template <int SEL>
__device__ __forceinline__ const float* sel_in(const float* p) {
    if (SEL == 0) return p;
    if (SEL == 1) return g_buf0;
    return g_buf1;
}
template <int SEL>
__device__ __forceinline__ float* sel_out(float* p) {
    if (SEL == 0) return p;
    if (SEL == 1) return g_buf0;
    return g_buf1;
}

__device__ __forceinline__ float cvt_rna_tf32(float x) {
    float r;
    asm("cvt.rna.tf32.f32 %0, %1;" : "=f"(r) : "f"(x));
    return r;
}

// ---------------------------------------------------------------------------
// tf32 tensor-core GEMM: z = in @ W^T  (no bias/act; commuted aggregation).
// mma.sync.m16n8k8.row.col. Block: 256 thr, BM=64, warps 4x2.
// ---------------------------------------------------------------------------
template <int INSEL, int BN, int NT>
__global__ __launch_bounds__(256, 2)
void gcn_gemm_kernel(const float* __restrict__ in_p,
                     const float* __restrict__ W,
                     int n_out, int ldz) {
    constexpr int BM = 64;
    constexpr int K = D;
    constexpr int LDA = K + 4;   // 132
    extern __shared__ float sm[];
    float* As = sm;              // [BM][LDA]
    float* Ws = sm + BM * LDA;   // [BN][LDA]
    const uint32_t* Asu = (const uint32_t*)As;
    const uint32_t* Wsu = (const uint32_t*)Ws;

    const float* in = sel_in<INSEL>(in_p);
    int tid = threadIdx.x;
    int row_base = blockIdx.x * BM;

    for (int i = tid * 4; i < BN * K; i += 256 * 4) {
        int j = i / K, k = i % K;
        float4 v = (j < n_out) ? *(const float4*)(W + (size_t)j * K + k)
                               : make_float4(0.f, 0.f, 0.f, 0.f);
        v.x = cvt_rna_tf32(v.x); v.y = cvt_rna_tf32(v.y);
        v.z = cvt_rna_tf32(v.z); v.w = cvt_rna_tf32(v.w);
        *(float4*)(Ws + j * LDA + k) = v;
    }
    for (int i = tid * 4; i < BM * K; i += 256 * 4) {
        int r = i / K, k = i % K;
        int g = row_base + r;
        float4 v = (g < N_NODES) ? *(const float4*)(in + (size_t)g * K + k)
                                 : make_float4(0.f, 0.f, 0.f, 0.f);
        v.x = cvt_rna_tf32(v.x); v.y = cvt_rna_tf32(v.y);
        v.z = cvt_rna_tf32(v.z); v.w = cvt_rna_tf32(v.w);
        *(float4*)(As + r * LDA + k) = v;
    }
    __syncthreads();

    int wid = tid >> 5;
    int lane = tid & 31;
    int wr = wid & 3;
    int wc = wid >> 2;
    int r0 = wr * 16;
    int c0 = wc * (NT * 8);
    int gid = lane >> 2;
    int tig = lane & 3;

    float acc[NT][4];
#pragma unroll
    for (int nt = 0; nt < NT; nt++)
#pragma unroll
        for (int q = 0; q < 4; q++) acc[nt][q] = 0.f;

#pragma unroll 4
    for (int k0 = 0; k0 < K; k0 += 8) {
        uint32_t a0 = Asu[(r0 + gid) * LDA + k0 + tig];
        uint32_t a1 = Asu[(r0 + gid + 8) * LDA + k0 + tig];
        uint32_t a2 = Asu[(r0 + gid) * LDA + k0 + tig + 4];
        uint32_t a3 = Asu[(r0 + gid + 8) * LDA + k0 + tig + 4];
#pragma unroll
        for (int nt = 0; nt < NT; nt++) {
            uint32_t b0 = Wsu[(c0 + nt * 8 + gid) * LDA + k0 + tig];
            uint32_t b1 = Wsu[(c0 + nt * 8 + gid) * LDA + k0 + tig + 4];
            asm volatile(
                "mma.sync.aligned.m16n8k8.row.col.f32.tf32.tf32.f32 "
                "{%0,%1,%2,%3}, {%4,%5,%6,%7}, {%8,%9}, {%0,%1,%2,%3};"
                : "+f"(acc[nt][0]), "+f"(acc[nt][1]),
                  "+f"(acc[nt][2]), "+f"(acc[nt][3])
                : "r"(a0), "r"(a1), "r"(a2), "r"(a3), "r"(b0), "r"(b1));
        }
    }

    int grow0 = row_base + r0 + gid;
    int grow1 = grow0 + 8;
#pragma unroll
    for (int nt = 0; nt < NT; nt++) {
        int j = c0 + nt * 8 + tig * 2;
        if (j < n_out) {
            if (grow0 < N_NODES) {
                float2 v = make_float2(acc[nt][0], acc[nt][1]);
                *(float2*)(g_acc + (size_t)grow0 * ldz + j) = v;
            }
            if (grow1 < N_NODES) {
                float2 v = make_float2(acc[nt][2], acc[nt][3]);
                *(float2*)(g_acc + (size_t)grow1 * ldz + j) = v;
            }
        }
    }
}

// ---------------------------------------------------------------------------
// Gather over z, fused bias + activation, 8-deep MLP:
//   out[n] = act( z[n] + sum_{s in nbrs(n)} z[s] + b )
// ---------------------------------------------------------------------------
template <int OUTSEL, int NOUT, bool RELU>
__global__ void gcn_gather_kernel(const float* __restrict__ bias,
                                  float* __restrict__ out_p) {
    constexpr int NV = (NOUT + 3) / 4;
    int node = blockIdx.x * (blockDim.x >> 5) + (threadIdx.x >> 5);
    if (node >= N_NODES) return;
    int lane = threadIdx.x & 31;
    bool act = (NV >= 32) || (lane < NV);
    int beg = g_row[node];
    int end = g_row[node + 1];

    float4 acc = make_float4(0.f, 0.f, 0.f, 0.f);
    float4 bv = make_float4(0.f, 0.f, 0.f, 0.f);
    if (act) {
        acc = *(const float4*)(g_acc + (size_t)node * NOUT + lane * 4);  // self
        bv = *(const float4*)(bias + lane * 4);
    }
    int i = beg;
    // 8 independent row loads in flight (~4 KB MLP per warp)
    for (; i + 8 <= end; i += 8) {
        int s0 = g_esrc[i],     s1 = g_esrc[i + 1];
        int s2 = g_esrc[i + 2], s3 = g_esrc[i + 3];
        int s4 = g_esrc[i + 4], s5 = g_esrc[i + 5];
        int s6 = g_esrc[i + 6], s7 = g_esrc[i + 7];
        if (act) {
            float4 v0 = *(const float4*)(g_acc + (size_t)s0 * NOUT + lane * 4);
            float4 v1 = *(const float4*)(g_acc + (size_t)s1 * NOUT + lane * 4);
            float4 v2 = *(const float4*)(g_acc + (size_t)s2 * NOUT + lane * 4);
            float4 v3 = *(const float4*)(g_acc + (size_t)s3 * NOUT + lane * 4);
            float4 v4 = *(const float4*)(g_acc + (size_t)s4 * NOUT + lane * 4);
            float4 v5 = *(const float4*)(g_acc + (size_t)s5 * NOUT + lane * 4);
            float4 v6 = *(const float4*)(g_acc + (size_t)s6 * NOUT + lane * 4);
            float4 v7 = *(const float4*)(g_acc + (size_t)s7 * NOUT + lane * 4);
            float4 t0, t1;
            t0.x = (v0.x + v1.x) + (v2.x + v3.x);
            t0.y = (v0.y + v1.y) + (v2.y + v3.y);
            t0.z = (v0.z + v1.z) + (v2.z + v3.z);
            t0.w = (v0.w + v1.w) + (v2.w + v3.w);
            t1.x = (v4.x + v5.x) + (v6.x + v7.x);
            t1.y = (v4.y + v5.y) + (v6.y + v7.y);
            t1.z = (v4.z + v5.z) + (v6.z + v7.z);
            t1.w = (v4.w + v5.w) + (v6.w + v7.w);
            acc.x += t0.x + t1.x;
            acc.y += t0.y + t1.y;
            acc.z += t0.z + t1.z;
            acc.w += t0.w + t1.w;
        }
    }
    for (; i + 4 <= end; i += 4) {
        int s0 = g_esrc[i], s1 = g_esrc[i + 1], s2 = g_esrc[i + 2], s3 = g_esrc[i + 3];
        if (act) {
            float4 v0 = *(const float4*)(g_acc + (size_t)s0 * NOUT + lane * 4);
            float4 v1 = *(const float4*)(g_acc + (size_t)s1 * NOUT + lane * 4);
            float4 v2 = *(const float4*)(g_acc + (size_t)s2 * NOUT + lane * 4);
            float4 v3 = *(const float4*)(g_acc + (size_t)s3 * NOUT + lane * 4);
            acc.x += (v0.x + v1.x) + (v2.x + v3.x);
            acc.y += (v0.y + v1.y) + (v2.y + v3.y);
            acc.z += (v0.z + v1.z) + (v2.z + v3.z);
            acc.w += (v0.w + v1.w) + (v2.w + v3.w);
        }
    }
    for (; i < end; i++) {
        int s = g_esrc[i];
        if (act) {
            float4 v = *(const float4*)(g_acc + (size_t)s * NOUT + lane * 4);
            acc.x += v.x; acc.y += v.y; acc.z += v.z; acc.w += v.w;
        }
    }
    if (act) {
        acc.x += bv.x; acc.y += bv.y; acc.z += bv.z; acc.w += bv.w;
        if (RELU) {
            acc.x = fmaxf(acc.x, 0.f); acc.y = fmaxf(acc.y, 0.f);
            acc.z = fmaxf(acc.z, 0.f); acc.w = fmaxf(acc.w, 0.f);
        }
        float* outp = sel_out<OUTSEL>(out_p);
        *(float4*)(outp + (size_t)node * NOUT + lane * 4) = acc;
    }
}

// ---------------------------------------------------------------------------
extern "C" void kernel_launch(void* const* d_in, const int* in_sizes, int n_in,
                              void* d_out, int out_size) {
    const float* x  = (const float*)d_in[0];
    const int* src  = (const int*)d_in[1];
    const int* dst  = (const int*)d_in[2];
    const float* W0 = (const float*)d_in[3];
    const float* b0 = (const float*)d_in[4];
    const float* W1 = (const float*)d_in[5];
    const float* b1 = (const float*)d_in[6];
    const float* W2 = (const float*)d_in[7];
    const float* b2 = (const float*)d_in[8];
    float* out = (float*)d_out;
    int n_edges = in_sizes[1];

    constexpr int SMEM_BIG   = (64 * 132 + 128 * 132) * 4;  // 101376 B -> 2 CTA/SM
    constexpr int SMEM_SMALL = (64 * 132 + 64 * 132) * 4;   //  67584 B
    static cudaStream_t s1 = nullptr;
    static cudaEvent_t e_fork = nullptr, e_csr = nullptr;
    if (!s1) {
        cudaFuncSetAttribute(gcn_gemm_kernel<0, 128, 8>,
                             cudaFuncAttributeMaxDynamicSharedMemorySize, SMEM_BIG);
        cudaFuncSetAttribute(gcn_gemm_kernel<1, 128, 8>,
                             cudaFuncAttributeMaxDynamicSharedMemorySize, SMEM_BIG);
        cudaFuncSetAttribute(gcn_gemm_kernel<2, 64, 4>,
                             cudaFuncAttributeMaxDynamicSharedMemorySize, SMEM_SMALL);
        cudaStreamCreateWithFlags(&s1, cudaStreamNonBlocking);
        cudaEventCreateWithFlags(&e_fork, cudaEventDisableTiming);
        cudaEventCreateWithFlags(&e_csr, cudaEventDisableTiming);
    }

    void* cnt_ptr = nullptr;
    cudaGetSymbolAddress(&cnt_ptr, g_cnt);

    int hist_blocks = ((n_edges + 3) / 4 + 255) / 256;
    int gath_blocks = (N_NODES + 7) / 8;
    int gemm_blocks = (N_NODES + 63) / 64;

    // Fork: CSR build on s1, concurrent with GEMM0 on main.
    cudaEventRecord(e_fork, 0);
    cudaStreamWaitEvent(s1, e_fork, 0);
    cudaMemsetAsync(cnt_ptr, 0, N_NODES * sizeof(int), s1);
    gcn_hist_kernel<<<hist_blocks, 256, 0, s1>>>(dst, n_edges);
    gcn_scanA_kernel<<<SCAN_NBLK, SCAN_BLK, 0, s1>>>();
    gcn_scanB_kernel<<<SCAN_NBLK, SCAN_BLK, 0, s1>>>();
    gcn_fill_kernel<<<hist_blocks, 256, 0, s1>>>(src, dst, n_edges);
    cudaEventRecord(e_csr, s1);

    // GEMM0 (independent of CSR): z = x W0^T
    gcn_gemm_kernel<0, 128, 8><<<gemm_blocks, 256, SMEM_BIG>>>(x, W0, D, D);
    cudaStreamWaitEvent(0, e_csr, 0);

    // Layer 0 gather: h1 = relu(z + A z + b0) -> g_buf0
    gcn_gather_kernel<1, 128, true><<<gath_blocks, 256>>>(b0, nullptr);
    // Layer 1: z = h1 W1^T ; h2 = relu(z + A z + b1) -> g_buf1
    gcn_gemm_kernel<1, 128, 8><<<gemm_blocks, 256, SMEM_BIG>>>(nullptr, W1, D, D);
    gcn_gather_kernel<2, 128, true><<<gath_blocks, 256>>>(b1, nullptr);
    // Layer 2 (head): z = h2 W2^T (40-wide) ; out = z + A z + b2
    gcn_gemm_kernel<2, 64, 4><<<gemm_blocks, 256, SMEM_SMALL>>>(
        nullptr, W2, N_CLASSES, N_CLASSES);
    gcn_gather_kernel<0, N_CLASSES, false><<<gath_blocks, 256>>>(b2, out);
}

// round 17
// speedup vs baseline: 1.0342x; 1.0342x over previous
#include <cuda_runtime.h>
#include <cuda_bf16.h>
#include <cstdint>

#define N_NODES 50000
#define N_EDGES_MAX 600000
#define D 128
#define N_CLASSES 40

#define SCAN_BLK 1024
#define SCAN_NBLK ((N_NODES + SCAN_BLK - 1) / SCAN_BLK)   // 49

// Scratch (static device globals — no allocations allowed).
// Only dereferenced from DEVICE code; host only takes addresses via API.
__device__ float g_acc[N_NODES * D];   // z = h W^T (GEMM output / gather input)
__device__ float g_buf0[N_NODES * D];  // h1
__device__ float g_buf1[N_NODES * D];  // h2
__device__ int   g_cnt[N_NODES];
__device__ int   g_row[N_NODES + 1];
__device__ int   g_cur[N_NODES];
__device__ int   g_esrc[N_EDGES_MAX];
__device__ int   g_bsum[SCAN_NBLK];

// ---------------------------------------------------------------------------
// CSR build — 1 edge per thread (4 waves: latency overlap on atomic chains)
// ---------------------------------------------------------------------------
__global__ void gcn_hist_kernel(const int* __restrict__ dst, int n_edges) {
    int e = blockIdx.x * blockDim.x + threadIdx.x;
    if (e < n_edges) atomicAdd(&g_cnt[dst[e]], 1);
}

// scanA: warp-shuffle block scan (2 barriers instead of 20).
__global__ void gcn_scanA_kernel() {
    __shared__ int warp_sums[32];
    int t = threadIdx.x;
    int idx = blockIdx.x * SCAN_BLK + t;
    int v = (idx < N_NODES) ? g_cnt[idx] : 0;
    int x = v;
#pragma unroll
    for (int off = 1; off < 32; off <<= 1) {
        int y = __shfl_up_sync(0xFFFFFFFFu, x, off);
        if ((t & 31) >= off) x += y;
    }
    if ((t & 31) == 31) warp_sums[t >> 5] = x;
    __syncthreads();
    if (t < 32) {
        int w = warp_sums[t];
#pragma unroll
        for (int off = 1; off < 32; off <<= 1) {
            int y = __shfl_up_sync(0xFFFFFFFFu, w, off);
            if (t >= off) w += y;
        }
        warp_sums[t] = w;
    }
    __syncthreads();
    int base = (t >= 32) ? warp_sums[(t >> 5) - 1] : 0;
    int incl = x + base;
    if (idx < N_NODES) g_row[idx] = incl - v;   // exclusive within block
    if (t == SCAN_BLK - 1) g_bsum[blockIdx.x] = incl;
}

__global__ void gcn_scanB_kernel() {
    __shared__ int sh[64];
    __shared__ int s_off;
    int t = threadIdx.x;
    int blk = blockIdx.x;
    if (t < 64) sh[t] = (t < SCAN_NBLK) ? g_bsum[t] : 0;
    __syncthreads();
    if (t == 0) {
        int o = 0;
#pragma unroll 7
        for (int b = 0; b < blk; b++) o += sh[b];
        s_off = o;
    }
    __syncthreads();
    int off = s_off;
    int idx = blk * SCAN_BLK + t;
    if (idx < N_NODES) {
        int r = g_row[idx] + off;
        g_row[idx] = r;
        g_cur[idx] = r;
        if (idx == N_NODES - 1) g_row[N_NODES] = r + g_cnt[idx];
    }
}

__global__ void gcn_fill_kernel(const int* __restrict__ src,
                                const int* __restrict__ dst, int n_edges) {
    int e = blockIdx.x * blockDim.x + threadIdx.x;
    if (e < n_edges) {
        int pos = atomicAdd(&g_cur[dst[e]], 1);
        g_esrc[pos] = src[e];
    }
}

// ---------------------------------------------------------------------------
// Buffer selection by template (device-symbol addresses stay device-side).
// SEL: 0 = param pointer, 1 = g_buf0, 2 = g_buf1
// ---------------------------------------------------------------------------
template <int SEL>
__device__ __forceinline__ const float* sel_in(const float* p) {
    if (SEL == 0) return p;
    if (SEL == 1) return g_buf0;
    return g_buf1;
}
template <int SEL>
__device__ __forceinline__ float* sel_out(float* p) {
    if (SEL == 0) return p;
    if (SEL == 1) return g_buf0;
    return g_buf1;
}

__device__ __forceinline__ float cvt_rna_tf32(float x) {
    float r;
    asm("cvt.rna.tf32.f32 %0, %1;" : "=f"(r) : "f"(x));
    return r;
}

// ---------------------------------------------------------------------------
// tf32 tensor-core GEMM: z = in @ W^T  (no bias/act; commuted aggregation).
// mma.sync.m16n8k8.row.col. Block: 256 thr, BM=64, warps 4x2.
// ---------------------------------------------------------------------------
template <int INSEL, int BN, int NT>
__global__ __launch_bounds__(256, 2)
void gcn_gemm_kernel(const float* __restrict__ in_p,
                     const float* __restrict__ W,
                     int n_out, int ldz) {
    constexpr int BM = 64;
    constexpr int K = D;
    constexpr int LDA = K + 4;   // 132
    extern __shared__ float sm[];
    float* As = sm;              // [BM][LDA]
    float* Ws = sm + BM * LDA;   // [BN][LDA]
    const uint32_t* Asu = (const uint32_t*)As;
    const uint32_t* Wsu = (const uint32_t*)Ws;

    const float* in = sel_in<INSEL>(in_p);
    int tid = threadIdx.x;
    int row_base = blockIdx.x * BM;

    for (int i = tid * 4; i < BN * K; i += 256 * 4) {
        int j = i / K, k = i % K;
        float4 v = (j < n_out) ? *(const float4*)(W + (size_t)j * K + k)
                               : make_float4(0.f, 0.f, 0.f, 0.f);
        v.x = cvt_rna_tf32(v.x); v.y = cvt_rna_tf32(v.y);
        v.z = cvt_rna_tf32(v.z); v.w = cvt_rna_tf32(v.w);
        *(float4*)(Ws + j * LDA + k) = v;
    }
    for (int i = tid * 4; i < BM * K; i += 256 * 4) {
        int r = i / K, k = i % K;
        int g = row_base + r;
        float4 v = (g < N_NODES) ? *(const float4*)(in + (size_t)g * K + k)
                                 : make_float4(0.f, 0.f, 0.f, 0.f);
        v.x = cvt_rna_tf32(v.x); v.y = cvt_rna_tf32(v.y);
        v.z = cvt_rna_tf32(v.z); v.w = cvt_rna_tf32(v.w);
        *(float4*)(As + r * LDA + k) = v;
    }
    __syncthreads();

    int wid = tid >> 5;
    int lane = tid & 31;
    int wr = wid & 3;
    int wc = wid >> 2;
    int r0 = wr * 16;
    int c0 = wc * (NT * 8);
    int gid = lane >> 2;
    int tig = lane & 3;

    float acc[NT][4];
#pragma unroll
    for (int nt = 0; nt < NT; nt++)
#pragma unroll
        for (int q = 0; q < 4; q++) acc[nt][q] = 0.f;

#pragma unroll 4
    for (int k0 = 0; k0 < K; k0 += 8) {
        uint32_t a0 = Asu[(r0 + gid) * LDA + k0 + tig];
        uint32_t a1 = Asu[(r0 + gid + 8) * LDA + k0 + tig];
        uint32_t a2 = Asu[(r0 + gid) * LDA + k0 + tig + 4];
        uint32_t a3 = Asu[(r0 + gid + 8) * LDA + k0 + tig + 4];
#pragma unroll
        for (int nt = 0; nt < NT; nt++) {
            uint32_t b0 = Wsu[(c0 + nt * 8 + gid) * LDA + k0 + tig];
            uint32_t b1 = Wsu[(c0 + nt * 8 + gid) * LDA + k0 + tig + 4];
            asm volatile(
                "mma.sync.aligned.m16n8k8.row.col.f32.tf32.tf32.f32 "
                "{%0,%1,%2,%3}, {%4,%5,%6,%7}, {%8,%9}, {%0,%1,%2,%3};"
                : "+f"(acc[nt][0]), "+f"(acc[nt][1]),
                  "+f"(acc[nt][2]), "+f"(acc[nt][3])
                : "r"(a0), "r"(a1), "r"(a2), "r"(a3), "r"(b0), "r"(b1));
        }
    }

    int grow0 = row_base + r0 + gid;
    int grow1 = grow0 + 8;
#pragma unroll
    for (int nt = 0; nt < NT; nt++) {
        int j = c0 + nt * 8 + tig * 2;
        if (j < n_out) {
            if (grow0 < N_NODES) {
                float2 v = make_float2(acc[nt][0], acc[nt][1]);
                *(float2*)(g_acc + (size_t)grow0 * ldz + j) = v;
            }
            if (grow1 < N_NODES) {
                float2 v = make_float2(acc[nt][2], acc[nt][3]);
                *(float2*)(g_acc + (size_t)grow1 * ldz + j) = v;
            }
        }
    }
}

// ---------------------------------------------------------------------------
// Gather over z, fused bias + activation (4-deep MLP — measured optimum):
//   out[n] = act( z[n] + sum_{s in nbrs(n)} z[s] + b )
// ---------------------------------------------------------------------------
template <int OUTSEL, int NOUT, bool RELU>
__global__ void gcn_gather_kernel(const float* __restrict__ bias,
                                  float* __restrict__ out_p) {
    constexpr int NV = (NOUT + 3) / 4;
    int node = blockIdx.x * (blockDim.x >> 5) + (threadIdx.x >> 5);
    if (node >= N_NODES) return;
    int lane = threadIdx.x & 31;
    bool act = (NV >= 32) || (lane < NV);
    int beg = g_row[node];
    int end = g_row[node + 1];

    float4 acc = make_float4(0.f, 0.f, 0.f, 0.f);
    float4 bv = make_float4(0.f, 0.f, 0.f, 0.f);
    if (act) {
        acc = *(const float4*)(g_acc + (size_t)node * NOUT + lane * 4);  // self
        bv = *(const float4*)(bias + lane * 4);
    }
    int i = beg;
    for (; i + 4 <= end; i += 4) {
        int s0 = g_esrc[i], s1 = g_esrc[i + 1], s2 = g_esrc[i + 2], s3 = g_esrc[i + 3];
        if (act) {
            float4 v0 = *(const float4*)(g_acc + (size_t)s0 * NOUT + lane * 4);
            float4 v1 = *(const float4*)(g_acc + (size_t)s1 * NOUT + lane * 4);
            float4 v2 = *(const float4*)(g_acc + (size_t)s2 * NOUT + lane * 4);
            float4 v3 = *(const float4*)(g_acc + (size_t)s3 * NOUT + lane * 4);
            acc.x += (v0.x + v1.x) + (v2.x + v3.x);
            acc.y += (v0.y + v1.y) + (v2.y + v3.y);
            acc.z += (v0.z + v1.z) + (v2.z + v3.z);
            acc.w += (v0.w + v1.w) + (v2.w + v3.w);
        }
    }
    for (; i < end; i++) {
        int s = g_esrc[i];
        if (act) {
            float4 v = *(const float4*)(g_acc + (size_t)s * NOUT + lane * 4);
            acc.x += v.x; acc.y += v.y; acc.z += v.z; acc.w += v.w;
        }
    }
    if (act) {
        acc.x += bv.x; acc.y += bv.y; acc.z += bv.z; acc.w += bv.w;
        if (RELU) {
            acc.x = fmaxf(acc.x, 0.f); acc.y = fmaxf(acc.y, 0.f);
            acc.z = fmaxf(acc.z, 0.f); acc.w = fmaxf(acc.w, 0.f);
        }
        float* outp = sel_out<OUTSEL>(out_p);
        *(float4*)(outp + (size_t)node * NOUT + lane * 4) = acc;
    }
}

// ---------------------------------------------------------------------------
extern "C" void kernel_launch(void* const* d_in, const int* in_sizes, int n_in,
                              void* d_out, int out_size) {
    const float* x  = (const float*)d_in[0];
    const int* src  = (const int*)d_in[1];
    const int* dst  = (const int*)d_in[2];
    const float* W0 = (const float*)d_in[3];
    const float* b0 = (const float*)d_in[4];
    const float* W1 = (const float*)d_in[5];
    const float* b1 = (const float*)d_in[6];
    const float* W2 = (const float*)d_in[7];
    const float* b2 = (const float*)d_in[8];
    float* out = (float*)d_out;
    int n_edges = in_sizes[1];

    constexpr int SMEM_BIG   = (64 * 132 + 128 * 132) * 4;  // 101376 B -> 2 CTA/SM
    constexpr int SMEM_SMALL = (64 * 132 + 64 * 132) * 4;   //  67584 B
    static cudaStream_t s1 = nullptr;
    static cudaEvent_t e_fork = nullptr, e_csr = nullptr;
    if (!s1) {
        cudaFuncSetAttribute(gcn_gemm_kernel<0, 128, 8>,
                             cudaFuncAttributeMaxDynamicSharedMemorySize, SMEM_BIG);
        cudaFuncSetAttribute(gcn_gemm_kernel<1, 128, 8>,
                             cudaFuncAttributeMaxDynamicSharedMemorySize, SMEM_BIG);
        cudaFuncSetAttribute(gcn_gemm_kernel<2, 64, 4>,
                             cudaFuncAttributeMaxDynamicSharedMemorySize, SMEM_SMALL);
        cudaStreamCreateWithFlags(&s1, cudaStreamNonBlocking);
        cudaEventCreateWithFlags(&e_fork, cudaEventDisableTiming);
        cudaEventCreateWithFlags(&e_csr, cudaEventDisableTiming);
    }

    void* cnt_ptr = nullptr;
    cudaGetSymbolAddress(&cnt_ptr, g_cnt);

    int edge_blocks = (n_edges + 255) / 256;   // 1 edge per thread
    int gath_blocks = (N_NODES + 7) / 8;
    int gemm_blocks = (N_NODES + 63) / 64;

    // Fork: CSR build on s1, concurrent with GEMM0 on main.
    cudaEventRecord(e_fork, 0);
    cudaStreamWaitEvent(s1, e_fork, 0);
    cudaMemsetAsync(cnt_ptr, 0, N_NODES * sizeof(int), s1);
    gcn_hist_kernel<<<edge_blocks, 256, 0, s1>>>(dst, n_edges);
    gcn_scanA_kernel<<<SCAN_NBLK, SCAN_BLK, 0, s1>>>();
    gcn_scanB_kernel<<<SCAN_NBLK, SCAN_BLK, 0, s1>>>();
    gcn_fill_kernel<<<edge_blocks, 256, 0, s1>>>(src, dst, n_edges);
    cudaEventRecord(e_csr, s1);

    // GEMM0 (independent of CSR): z = x W0^T
    gcn_gemm_kernel<0, 128, 8><<<gemm_blocks, 256, SMEM_BIG>>>(x, W0, D, D);
    cudaStreamWaitEvent(0, e_csr, 0);

    // Layer 0 gather: h1 = relu(z + A z + b0) -> g_buf0
    gcn_gather_kernel<1, 128, true><<<gath_blocks, 256>>>(b0, nullptr);
    // Layer 1: z = h1 W1^T ; h2 = relu(z + A z + b1) -> g_buf1
    gcn_gemm_kernel<1, 128, 8><<<gemm_blocks, 256, SMEM_BIG>>>(nullptr, W1, D, D);
    gcn_gather_kernel<2, 128, true><<<gath_blocks, 256>>>(b1, nullptr);
    // Layer 2 (head): z = h2 W2^T (40-wide) ; out = z + A z + b2
    gcn_gemm_kernel<2, 64, 4><<<gemm_blocks, 256, SMEM_SMALL>>>(
        nullptr, W2, N_CLASSES, N_CLASSES);
    gcn_gather_kernel<0, N_CLASSES, false><<<gath_blocks, 256>>>(b2, out);
}